// round 7
// baseline (speedup 1.0000x reference)
#include <cuda_runtime.h>
#include <cuda_bf16.h>
#include <cstdint>

#define N_ATOMS 50000
#define N_PAIRS 800000
#define N_EMB   128
#define N_DIST  100
#define N_HID   128
#define BSTR    136          // padded bf16 row stride (272 B)
#define NTILES  8            // pair tiles per CTA
#define NTILE_TOT (N_PAIRS / 128)

typedef unsigned long long ull;
typedef unsigned short ushort_t;

// ---------------- device scratch ----------------
__device__ float g_afh[(size_t)N_ATOMS * N_HID];                    // 25.6 MB
// n-major (transposed) padded bf16 images of W_df / W_fc, hi+lo splits
__device__ __align__(16) __nv_bfloat16 g_Bdf_hi[128 * BSTR];
__device__ __align__(16) __nv_bfloat16 g_Bdf_lo[128 * BSTR];
__device__ __align__(16) __nv_bfloat16 g_Bfc_hi[128 * BSTR];
__device__ __align__(16) __nv_bfloat16 g_Bfc_lo[128 * BSTR];

// ---------------- f32x2 helpers (atoms kernel) ----------------
static __device__ __forceinline__ void ffma2(ull &acc, ull a, ull b) {
    asm("fma.rn.f32x2 %0, %1, %2, %0;" : "+l"(acc) : "l"(a), "l"(b));
}
static __device__ __forceinline__ ull mul2(ull a, ull b) {
    ull r; asm("mul.rn.f32x2 %0, %1, %2;" : "=l"(r) : "l"(a), "l"(b)); return r;
}
static __device__ __forceinline__ ull pack2(float lo, float hi) {
    ull r; asm("mov.b64 %0, {%1, %2};" : "=l"(r) : "f"(lo), "f"(hi)); return r;
}
static __device__ __forceinline__ ull dup2(float v) {
    ull r; asm("mov.b64 %0, {%1, %1};" : "=l"(r) : "f"(v)); return r;
}
static __device__ __forceinline__ void unpack2(ull p, float &lo, float &hi) {
    asm("mov.b64 {%0, %1}, %2;" : "=f"(lo), "=f"(hi) : "l"(p));
}
static __device__ __forceinline__ float fast_tanh(float x) {
    float e = __expf(2.0f * x);
    return 1.0f - __fdividef(2.0f, e + 1.0f);
}
static __device__ __forceinline__ void split_bf(float x, ushort_t &h, ushort_t &l) {
    __nv_bfloat16 bh = __float2bfloat16(x);
    float r = x - __bfloat162float(bh);
    __nv_bfloat16 bl = __float2bfloat16(r);
    h = __bfloat16_as_ushort(bh);
    l = __bfloat16_as_ushort(bl);
}

// ---------------- mma / ldmatrix wrappers (sm_80+ features) ----------------
static __device__ __forceinline__ uint32_t smem_u32(const void* p) {
    uint32_t a;
    asm("{ .reg .u64 t; cvta.to.shared.u64 t, %1; cvt.u32.u64 %0, t; }"
        : "=r"(a) : "l"(p));
    return a;
}
static __device__ __forceinline__ void ldsm4(uint32_t* r, uint32_t addr) {
    asm volatile("ldmatrix.sync.aligned.m8n8.x4.shared.b16 {%0,%1,%2,%3}, [%4];"
                 : "=r"(r[0]), "=r"(r[1]), "=r"(r[2]), "=r"(r[3]) : "r"(addr));
}
static __device__ __forceinline__ void mma16816(float* d, const uint32_t* a,
                                                const uint32_t* b) {
    asm volatile(
        "mma.sync.aligned.m16n8k16.row.col.f32.bf16.bf16.f32 "
        "{%0,%1,%2,%3}, {%4,%5,%6,%7}, {%8,%9}, {%0,%1,%2,%3};"
        : "+f"(d[0]), "+f"(d[1]), "+f"(d[2]), "+f"(d[3])
        : "r"(a[0]), "r"(a[1]), "r"(a[2]), "r"(a[3]), "r"(b[0]), "r"(b[1]));
}

// ---------------- SMEM layout for pairs kernel (bytes) ----------------
#define SM_IS     0                        // 128 int
#define SM_JS     512                      // 128 int
#define SM_BDF    1024                     // 128 float
#define SM_AHI    2048                     // 34816 B
#define SM_ALO    (SM_AHI + 34816)         // 36864
#define SM_BDFHI  (SM_ALO + 34816)         // 71680
#define SM_BDFLO  (SM_BDFHI + 34816)       // 106496
#define SM_BFCHI  (SM_BDFLO + 34816)       // 141312
#define SM_BFCLO  (SM_BFCHI + 34816)       // 176128
#define SM_TOTAL  (SM_BFCLO + 34816)       // 210944 B
#define SM_MSG    SM_AHI                   // fp32 msg 128x129 (66048 B) reuses A

// =====================================================================
// Prep: n-major padded bf16 hi/lo images of W_df^T and W_fc^T
// =====================================================================
__global__ void prep_kernel(const float* __restrict__ W_df,
                            const float* __restrict__ W_fc)
{
    int idx = blockIdx.x * blockDim.x + threadIdx.x;   // 0..16383
    if (idx >= 16384) return;
    int n = idx >> 7;
    int k = idx & 127;
    int o = n * BSTR + k;
    float vdf = (k < N_DIST) ? W_df[k * 128 + n] : 0.0f;
    float vfc = W_fc[k * 128 + n];
    ushort_t h, l;
    split_bf(vdf, h, l);
    g_Bdf_hi[o] = __ushort_as_bfloat16(h);
    g_Bdf_lo[o] = __ushort_as_bfloat16(l);
    split_bf(vfc, h, l);
    g_Bfc_hi[o] = __ushort_as_bfloat16(h);
    g_Bfc_lo[o] = __ushort_as_bfloat16(l);
}

// =====================================================================
// Atoms kernel: unchanged FFMA2 path (passing since R2)
// =====================================================================
template<int SA>
static __device__ __forceinline__ void gemm_step8(
    const float* __restrict__ Arow, const float* __restrict__ Bk,
    int k, ull acc[32])
{
    ull a2[8];
#pragma unroll
    for (int i = 0; i < 8; i++) a2[i] = dup2(Arow[i * SA + k]);
    ulonglong2 b01 = *(const ulonglong2*)(Bk);
    ulonglong2 b23 = *(const ulonglong2*)(Bk + 4);
#pragma unroll
    for (int i = 0; i < 8; i++) {
        ffma2(acc[i * 4 + 0], a2[i], b01.x);
        ffma2(acc[i * 4 + 1], a2[i], b01.y);
        ffma2(acc[i * 4 + 2], a2[i], b23.x);
        ffma2(acc[i * 4 + 3], a2[i], b23.y);
    }
}

__global__ void __launch_bounds__(256, 1) atoms_kernel(
    const float* __restrict__ atom_features,
    const float* __restrict__ W_cf,
    const float* __restrict__ W_fc,
    const float* __restrict__ b_cf,
    const float* __restrict__ b_df,
    float* __restrict__ out)
{
    extern __shared__ float smem[];
    float* bcf_s = smem;
    float* bdf_s = smem + 128;
    float* Af    = smem + 256;
    float* Ms    = Af + 128 * 132;
    float* Bs    = Ms + 128 * 132;

    const int tid = threadIdx.x;
    const int tx = tid & 15, ty = tid >> 4;
    const int c0 = tx * 8, r0 = ty * 8;
    const int base = blockIdx.x * 128;
    const int rows = min(128, N_ATOMS - base);

    if (tid < 128) { bcf_s[tid] = b_cf[tid]; bdf_s[tid] = b_df[tid]; }
    for (int idx = tid; idx < 128 * 32; idx += 256) {
        int rr = idx >> 5, q = idx & 31;
        float4 v = make_float4(0.f, 0.f, 0.f, 0.f);
        if (rr < rows) v = ((const float4*)atom_features)[(size_t)(base + rr) * 32 + q];
        ((float4*)Af)[rr * 33 + q] = v;
        ((float4*)Bs)[idx] = ((const float4*)W_cf)[idx];
    }
    __syncthreads();

    ull acc[32];
    {
        ull b[4];
#pragma unroll
        for (int q = 0; q < 4; q++) b[q] = pack2(bcf_s[c0 + 2*q], bcf_s[c0 + 2*q + 1]);
#pragma unroll
        for (int i = 0; i < 8; i++)
#pragma unroll
            for (int q = 0; q < 4; q++) acc[i * 4 + q] = b[q];
    }
    {
        const float* Arow = Af + r0 * 132;
        const float* Bc   = Bs + c0;
#pragma unroll 2
        for (int k = 0; k < 128; k++) gemm_step8<132>(Arow, Bc + k * 128, k, acc);
    }
#pragma unroll
    for (int i = 0; i < 8; i++) {
        if (base + r0 + i < N_ATOMS) {
            ull* arow = (ull*)(g_afh + (size_t)(base + r0 + i) * N_HID + c0);
#pragma unroll
            for (int q = 0; q < 4; q++) arow[q] = acc[i * 4 + q];
        }
    }
    __syncthreads();
#pragma unroll
    for (int i = 0; i < 8; i++) {
        ulonglong2 m01, m23;
        m01.x = mul2(acc[i*4+0], pack2(bdf_s[c0+0], bdf_s[c0+1]));
        m01.y = mul2(acc[i*4+1], pack2(bdf_s[c0+2], bdf_s[c0+3]));
        m23.x = mul2(acc[i*4+2], pack2(bdf_s[c0+4], bdf_s[c0+5]));
        m23.y = mul2(acc[i*4+3], pack2(bdf_s[c0+6], bdf_s[c0+7]));
        *(ulonglong2*)(Ms + (r0 + i) * 132 + c0)     = m01;
        *(ulonglong2*)(Ms + (r0 + i) * 132 + c0 + 4) = m23;
    }
    for (int idx = tid; idx < 128 * 32; idx += 256)
        ((float4*)Bs)[idx] = ((const float4*)W_fc)[idx];
    __syncthreads();

#pragma unroll
    for (int i = 0; i < 32; i++) acc[i] = 0ULL;
    {
        const float* Arow = Ms + r0 * 132;
        const float* Bc   = Bs + c0;
#pragma unroll 2
        for (int k = 0; k < 128; k++) gemm_step8<132>(Arow, Bc + k * 128, k, acc);
    }
#pragma unroll
    for (int i = 0; i < 8; i++) {
        if (base + r0 + i < N_ATOMS) {
            float* orow = out + (size_t)(base + r0 + i) * N_EMB + c0;
            const float* af = Af + (r0 + i) * 132 + c0;
#pragma unroll
            for (int q = 0; q < 4; q++) {
                float lo, hi; unpack2(acc[i * 4 + q], lo, hi);
                orow[2 * q]     = af[2 * q]     - fast_tanh(lo);
                orow[2 * q + 1] = af[2 * q + 1] - fast_tanh(hi);
            }
        }
    }
}

// =====================================================================
// Warp GEMM: D[128,128] over 8 warps (2 row-groups x 4 col-groups).
// Warp tile 64x32: 4 m16 tiles x 4 n8 tiles, 3-term bf16 split.
// =====================================================================
template<int KSTEPS>
static __device__ __forceinline__ void do_gemm(
    uint32_t aHi, uint32_t aLo, uint32_t bHi, uint32_t bLo,
    uint32_t aoff0, uint32_t boff0, float* d)
{
#pragma unroll 1
    for (int ks = 0; ks < KSTEPS; ks++) {
        uint32_t Ah[4][4], Al[4][4], Bh[4][2], Bl[4][2];
#pragma unroll
        for (int mt = 0; mt < 4; mt++) {
            uint32_t off = aoff0 + mt * (16 * BSTR * 2) + ks * 32;
            ldsm4(Ah[mt], aHi + off);
            ldsm4(Al[mt], aLo + off);
        }
#pragma unroll
        for (int np = 0; np < 2; np++) {
            uint32_t off = boff0 + np * (16 * BSTR * 2) + ks * 32;
            uint32_t th[4], tl[4];
            ldsm4(th, bHi + off);
            ldsm4(tl, bLo + off);
            Bh[2*np][0] = th[0]; Bh[2*np][1] = th[1];
            Bh[2*np+1][0] = th[2]; Bh[2*np+1][1] = th[3];
            Bl[2*np][0] = tl[0]; Bl[2*np][1] = tl[1];
            Bl[2*np+1][0] = tl[2]; Bl[2*np+1][1] = tl[3];
        }
#pragma unroll
        for (int mt = 0; mt < 4; mt++)
#pragma unroll
            for (int nt = 0; nt < 4; nt++) {
                float* dd = d + (mt * 4 + nt) * 4;
                mma16816(dd, Ah[mt], Bh[nt]);   // hi*hi
                mma16816(dd, Ah[mt], Bl[nt]);   // hi*lo
                mma16816(dd, Al[mt], Bh[nt]);   // lo*hi
            }
    }
}

// =====================================================================
// Pairs kernel: persistent-W multi-tile. 256 thr = 8 warps.
// Both W images stay resident; each CTA processes NTILES tiles.
// =====================================================================
__global__ void __launch_bounds__(256, 1) pairs_kernel(
    const float* __restrict__ distance,
    const int*   __restrict__ dmi,
    const int*   __restrict__ dmj,
    const float* __restrict__ b_df,
    float* __restrict__ out)
{
    extern __shared__ char smc[];
    int*   i_s   = (int*)(smc + SM_IS);
    int*   j_s   = (int*)(smc + SM_JS);
    float* bdf_s = (float*)(smc + SM_BDF);
    const uint32_t sb  = smem_u32(smc);
    const uint32_t aHi = sb + SM_AHI, aLo = sb + SM_ALO;

    const int tid = threadIdx.x;
    const int wid = tid >> 5, lane = tid & 31;
    const int rg = wid >> 2, cg = wid & 3;

    // ---- one-time: stage all four W images + b_df ----
    if (tid < 128) bdf_s[tid] = b_df[tid];
    for (int q = tid; q < 2176; q += 256) {
        ((uint4*)(smc + SM_BDFHI))[q] = ((const uint4*)g_Bdf_hi)[q];
        ((uint4*)(smc + SM_BDFLO))[q] = ((const uint4*)g_Bdf_lo)[q];
        ((uint4*)(smc + SM_BFCHI))[q] = ((const uint4*)g_Bfc_hi)[q];
        ((uint4*)(smc + SM_BFCLO))[q] = ((const uint4*)g_Bfc_lo)[q];
    }

    // lane-level ldmatrix address components
    const int arow  = (lane & 7) + 8 * ((lane >> 3) & 1);
    const int acolb = 16 * (lane >> 4);
    const int brow  = (lane & 7) + 8 * (lane >> 4);
    const int bcolb = 16 * ((lane >> 3) & 1);
    const uint32_t aoff0 = (uint32_t)((rg * 64 + arow) * (BSTR * 2) + acolb);
    const uint32_t boff0 = (uint32_t)((cg * 32 + brow) * (BSTR * 2) + bcolb);

    const int t0 = blockIdx.x * NTILES;
    const int t1 = min(t0 + NTILES, NTILE_TOT);

    // staging split: 2 threads per row
    const int srow  = tid >> 1;
    const int shalf = tid & 1;
    const int q0 = shalf ? 13 : 0;
    const int q1 = shalf ? 25 : 13;

    for (int tile = t0; tile < t1; tile++) {
        const int pbase = tile * 128;

        // ---- stage: distance splits + indices (all 256 threads) ----
        __syncthreads();   // previous tile's msg reads done before overwrite
        {
            if (!shalf) {
                i_s[srow] = dmi[pbase + srow];
                j_s[srow] = dmj[pbase + srow];
            }
            const float4* dr =
                (const float4*)(distance + (size_t)(pbase + srow) * N_DIST);
            char* ah = smc + SM_AHI + srow * (BSTR * 2);
            char* al = smc + SM_ALO + srow * (BSTR * 2);
#pragma unroll
            for (int q = q0; q < q1; q++) {
                float4 v = dr[q];
                ushort_t h0,l0,h1,l1,h2,l2,h3,l3;
                split_bf(v.x, h0, l0); split_bf(v.y, h1, l1);
                split_bf(v.z, h2, l2); split_bf(v.w, h3, l3);
                *(unsigned*)(ah + 8 * q)     = (unsigned)h0 | ((unsigned)h1 << 16);
                *(unsigned*)(ah + 8 * q + 4) = (unsigned)h2 | ((unsigned)h3 << 16);
                *(unsigned*)(al + 8 * q)     = (unsigned)l0 | ((unsigned)l1 << 16);
                *(unsigned*)(al + 8 * q + 4) = (unsigned)l2 | ((unsigned)l3 << 16);
            }
            if (shalf) {
#pragma unroll
                for (int c = 100; c < 112; c += 2) {   // pad for kstep 6
                    *(unsigned*)(ah + c * 2) = 0u;
                    *(unsigned*)(al + c * 2) = 0u;
                }
            }
        }
        __syncthreads();

        // ---- GEMM1: dh = dist @ W_df (K=112 incl. zero pad) ----
        float d[64];
#pragma unroll
        for (int i = 0; i < 64; i++) d[i] = 0.0f;
        do_gemm<7>(aHi, aLo, sb + SM_BDFHI, sb + SM_BDFLO, aoff0, boff0, d);
        __syncthreads();   // A-region ldsm done before epilogue overwrite

        // ---- Epilogue 1: m = (dh + b_df) * afh[j]; resplit into A ----
        {
            const int g = lane >> 2, tg = lane & 3;
#pragma unroll
            for (int mt = 0; mt < 4; mt++)
#pragma unroll
                for (int f2 = 0; f2 < 2; f2++) {
                    const int row = rg * 64 + mt * 16 + 8 * f2 + g;
                    const int j = j_s[row];
                    const float* ar = g_afh + (size_t)j * N_HID;
                    char* ah = smc + SM_AHI + row * (BSTR * 2);
                    char* al = smc + SM_ALO + row * (BSTR * 2);
#pragma unroll
                    for (int nt = 0; nt < 4; nt++) {
                        const int c = cg * 32 + nt * 8 + 2 * tg;
                        float2 af = *(const float2*)(ar + c);
                        float v0 = (d[(mt*4+nt)*4 + 2*f2]     + bdf_s[c])     * af.x;
                        float v1 = (d[(mt*4+nt)*4 + 2*f2 + 1] + bdf_s[c + 1]) * af.y;
                        ushort_t h0, l0, h1, l1;
                        split_bf(v0, h0, l0); split_bf(v1, h1, l1);
                        *(unsigned*)(ah + c * 2) = (unsigned)h0 | ((unsigned)h1 << 16);
                        *(unsigned*)(al + c * 2) = (unsigned)l0 | ((unsigned)l1 << 16);
                    }
                }
        }
        __syncthreads();

        // ---- GEMM2: pre = m @ W_fc (K=128) ----
#pragma unroll
        for (int i = 0; i < 64; i++) d[i] = 0.0f;
        do_gemm<8>(aHi, aLo, sb + SM_BFCHI, sb + SM_BFCLO, aoff0, boff0, d);
        __syncthreads();   // A-region ldsm done before msg overwrite

        // ---- Epilogue 2: msg = tanh(pre) -> A region ----
        {
            float* msg = (float*)(smc + SM_MSG);
            const int g = lane >> 2, tg = lane & 3;
#pragma unroll
            for (int mt = 0; mt < 4; mt++)
#pragma unroll
                for (int f2 = 0; f2 < 2; f2++) {
                    const int row = rg * 64 + mt * 16 + 8 * f2 + g;
#pragma unroll
                    for (int nt = 0; nt < 4; nt++) {
                        const int c = cg * 32 + nt * 8 + 2 * tg;
                        msg[row * 129 + c]     = fast_tanh(d[(mt*4+nt)*4 + 2*f2]);
                        msg[row * 129 + c + 1] = fast_tanh(d[(mt*4+nt)*4 + 2*f2 + 1]);
                    }
                }
        }
        __syncthreads();

        // ---- Segment sum over sorted i: 128 cols x 2 halves ----
        {
            const float* msg = (const float*)(smc + SM_MSG);
            const int c  = tid & 127;
            const int h0 = (tid >> 7) * 64;
            int   cur = i_s[h0];
            float sum = 0.0f;
            for (int rr = h0; rr < h0 + 64; rr++) {
                int ii = i_s[rr];
                if (ii != cur) {
                    atomicAdd(out + (size_t)cur * N_EMB + c, sum);
                    cur = ii; sum = 0.0f;
                }
                sum += msg[rr * 129 + c];
            }
            atomicAdd(out + (size_t)cur * N_EMB + c, sum);
        }
    }
}

// =====================================================================
extern "C" void kernel_launch(void* const* d_in, const int* in_sizes, int n_in,
                              void* d_out, int out_size)
{
    const float* atom_features = (const float*)d_in[0];
    const float* distance      = (const float*)d_in[1];
    const int*   dmi           = (const int*)d_in[3];
    const int*   dmj           = (const int*)d_in[4];
    const float* W_cf          = (const float*)d_in[5];
    const float* W_df          = (const float*)d_in[6];
    const float* W_fc          = (const float*)d_in[7];
    const float* b_cf          = (const float*)d_in[8];
    const float* b_df          = (const float*)d_in[9];
    float*       out           = (float*)d_out;

    const int smemA = (256 + 128*132 + 128*132 + 128*128) * 4;   // 201728 B

    cudaFuncSetAttribute(atoms_kernel, cudaFuncAttributeMaxDynamicSharedMemorySize, smemA);
    cudaFuncSetAttribute(pairs_kernel, cudaFuncAttributeMaxDynamicSharedMemorySize, SM_TOTAL);

    prep_kernel<<<64, 256>>>(W_df, W_fc);
    atoms_kernel<<<(N_ATOMS + 127) / 128, 256, smemA>>>(
        atom_features, W_cf, W_fc, b_cf, b_df, out);
    const int gridP = (NTILE_TOT + NTILES - 1) / NTILES;
    pairs_kernel<<<gridP, 256, SM_TOTAL>>>(
        distance, dmi, dmj, b_df, out);
}

// round 8
// speedup vs baseline: 1.3161x; 1.3161x over previous
#include <cuda_runtime.h>
#include <cuda_bf16.h>
#include <cstdint>

#define N_ATOMS 50000
#define N_PAIRS 800000
#define N_EMB   128
#define N_DIST  100
#define N_HID   128
#define BSTR    136          // padded bf16 row stride (272 B)
#define TROWS   256          // pairs per CTA tile

typedef unsigned long long ull;
typedef unsigned short ushort_t;

// ---------------- device scratch ----------------
__device__ float g_afh[(size_t)N_ATOMS * N_HID];                    // 25.6 MB
__device__ __align__(16) __nv_bfloat16 g_Bdf_hi[128 * BSTR];
__device__ __align__(16) __nv_bfloat16 g_Bdf_lo[128 * BSTR];
__device__ __align__(16) __nv_bfloat16 g_Bfc_hi[128 * BSTR];
__device__ __align__(16) __nv_bfloat16 g_Bfc_lo[128 * BSTR];

// ---------------- f32x2 helpers (atoms kernel) ----------------
static __device__ __forceinline__ void ffma2(ull &acc, ull a, ull b) {
    asm("fma.rn.f32x2 %0, %1, %2, %0;" : "+l"(acc) : "l"(a), "l"(b));
}
static __device__ __forceinline__ ull mul2(ull a, ull b) {
    ull r; asm("mul.rn.f32x2 %0, %1, %2;" : "=l"(r) : "l"(a), "l"(b)); return r;
}
static __device__ __forceinline__ ull pack2(float lo, float hi) {
    ull r; asm("mov.b64 %0, {%1, %2};" : "=l"(r) : "f"(lo), "f"(hi)); return r;
}
static __device__ __forceinline__ ull dup2(float v) {
    ull r; asm("mov.b64 %0, {%1, %1};" : "=l"(r) : "f"(v)); return r;
}
static __device__ __forceinline__ void unpack2(ull p, float &lo, float &hi) {
    asm("mov.b64 {%0, %1}, %2;" : "=f"(lo), "=f"(hi) : "l"(p));
}
static __device__ __forceinline__ float fast_tanh(float x) {
    float e = __expf(2.0f * x);
    return 1.0f - __fdividef(2.0f, e + 1.0f);
}
static __device__ __forceinline__ void split_bf(float x, ushort_t &h, ushort_t &l) {
    __nv_bfloat16 bh = __float2bfloat16(x);
    float r = x - __bfloat162float(bh);
    __nv_bfloat16 bl = __float2bfloat16(r);
    h = __bfloat16_as_ushort(bh);
    l = __bfloat16_as_ushort(bl);
}

// ---------------- mma / ldmatrix wrappers (sm_80+ features) ----------------
static __device__ __forceinline__ uint32_t smem_u32(const void* p) {
    uint32_t a;
    asm("{ .reg .u64 t; cvta.to.shared.u64 t, %1; cvt.u32.u64 %0, t; }"
        : "=r"(a) : "l"(p));
    return a;
}
static __device__ __forceinline__ void ldsm4(uint32_t* r, uint32_t addr) {
    asm volatile("ldmatrix.sync.aligned.m8n8.x4.shared.b16 {%0,%1,%2,%3}, [%4];"
                 : "=r"(r[0]), "=r"(r[1]), "=r"(r[2]), "=r"(r[3]) : "r"(addr));
}
static __device__ __forceinline__ void mma16816(float* d, const uint32_t* a,
                                                const uint32_t* b) {
    asm volatile(
        "mma.sync.aligned.m16n8k16.row.col.f32.bf16.bf16.f32 "
        "{%0,%1,%2,%3}, {%4,%5,%6,%7}, {%8,%9}, {%0,%1,%2,%3};"
        : "+f"(d[0]), "+f"(d[1]), "+f"(d[2]), "+f"(d[3])
        : "r"(a[0]), "r"(a[1]), "r"(a[2]), "r"(a[3]), "r"(b[0]), "r"(b[1]));
}

// ---------------- SMEM layout for pairs kernel (bytes) ----------------
#define SM_IS    0                         // 256 int  (1024 B)
#define SM_JS    1024                      // 256 int  (1024 B)
#define SM_BDF   2048                      // 128 float (512 B)
#define SM_AHI   2560                      // 256 x 136 bf16 = 69632 B
#define SM_ALO   (SM_AHI + 69632)          // 72192
#define SM_BHI   (SM_ALO + 69632)          // 141824 (34816 B)
#define SM_BLO   (SM_BHI + 34816)          // 176640 (34816 B)
#define SM_TOTAL (SM_BLO + 34816)          // 211456 B
#define SM_MSG   SM_AHI                    // fp32 msg 256x129 (132096 B) reuses A

// =====================================================================
// Prep: n-major padded bf16 hi/lo images of W_df^T and W_fc^T
// =====================================================================
__global__ void prep_kernel(const float* __restrict__ W_df,
                            const float* __restrict__ W_fc)
{
    int idx = blockIdx.x * blockDim.x + threadIdx.x;   // 0..16383
    if (idx >= 16384) return;
    int n = idx >> 7;
    int k = idx & 127;
    int o = n * BSTR + k;
    float vdf = (k < N_DIST) ? W_df[k * 128 + n] : 0.0f;
    float vfc = W_fc[k * 128 + n];
    ushort_t h, l;
    split_bf(vdf, h, l);
    g_Bdf_hi[o] = __ushort_as_bfloat16(h);
    g_Bdf_lo[o] = __ushort_as_bfloat16(l);
    split_bf(vfc, h, l);
    g_Bfc_hi[o] = __ushort_as_bfloat16(h);
    g_Bfc_lo[o] = __ushort_as_bfloat16(l);
}

// =====================================================================
// Atoms kernel: unchanged FFMA2 path (passing since R2)
// =====================================================================
template<int SA>
static __device__ __forceinline__ void gemm_step8(
    const float* __restrict__ Arow, const float* __restrict__ Bk,
    int k, ull acc[32])
{
    ull a2[8];
#pragma unroll
    for (int i = 0; i < 8; i++) a2[i] = dup2(Arow[i * SA + k]);
    ulonglong2 b01 = *(const ulonglong2*)(Bk);
    ulonglong2 b23 = *(const ulonglong2*)(Bk + 4);
#pragma unroll
    for (int i = 0; i < 8; i++) {
        ffma2(acc[i * 4 + 0], a2[i], b01.x);
        ffma2(acc[i * 4 + 1], a2[i], b01.y);
        ffma2(acc[i * 4 + 2], a2[i], b23.x);
        ffma2(acc[i * 4 + 3], a2[i], b23.y);
    }
}

__global__ void __launch_bounds__(256, 1) atoms_kernel(
    const float* __restrict__ atom_features,
    const float* __restrict__ W_cf,
    const float* __restrict__ W_fc,
    const float* __restrict__ b_cf,
    const float* __restrict__ b_df,
    float* __restrict__ out)
{
    extern __shared__ float smem[];
    float* bcf_s = smem;
    float* bdf_s = smem + 128;
    float* Af    = smem + 256;
    float* Ms    = Af + 128 * 132;
    float* Bs    = Ms + 128 * 132;

    const int tid = threadIdx.x;
    const int tx = tid & 15, ty = tid >> 4;
    const int c0 = tx * 8, r0 = ty * 8;
    const int base = blockIdx.x * 128;
    const int rows = min(128, N_ATOMS - base);

    if (tid < 128) { bcf_s[tid] = b_cf[tid]; bdf_s[tid] = b_df[tid]; }
    for (int idx = tid; idx < 128 * 32; idx += 256) {
        int rr = idx >> 5, q = idx & 31;
        float4 v = make_float4(0.f, 0.f, 0.f, 0.f);
        if (rr < rows) v = ((const float4*)atom_features)[(size_t)(base + rr) * 32 + q];
        ((float4*)Af)[rr * 33 + q] = v;
        ((float4*)Bs)[idx] = ((const float4*)W_cf)[idx];
    }
    __syncthreads();

    ull acc[32];
    {
        ull b[4];
#pragma unroll
        for (int q = 0; q < 4; q++) b[q] = pack2(bcf_s[c0 + 2*q], bcf_s[c0 + 2*q + 1]);
#pragma unroll
        for (int i = 0; i < 8; i++)
#pragma unroll
            for (int q = 0; q < 4; q++) acc[i * 4 + q] = b[q];
    }
    {
        const float* Arow = Af + r0 * 132;
        const float* Bc   = Bs + c0;
#pragma unroll 2
        for (int k = 0; k < 128; k++) gemm_step8<132>(Arow, Bc + k * 128, k, acc);
    }
#pragma unroll
    for (int i = 0; i < 8; i++) {
        if (base + r0 + i < N_ATOMS) {
            ull* arow = (ull*)(g_afh + (size_t)(base + r0 + i) * N_HID + c0);
#pragma unroll
            for (int q = 0; q < 4; q++) arow[q] = acc[i * 4 + q];
        }
    }
    __syncthreads();
#pragma unroll
    for (int i = 0; i < 8; i++) {
        ulonglong2 m01, m23;
        m01.x = mul2(acc[i*4+0], pack2(bdf_s[c0+0], bdf_s[c0+1]));
        m01.y = mul2(acc[i*4+1], pack2(bdf_s[c0+2], bdf_s[c0+3]));
        m23.x = mul2(acc[i*4+2], pack2(bdf_s[c0+4], bdf_s[c0+5]));
        m23.y = mul2(acc[i*4+3], pack2(bdf_s[c0+6], bdf_s[c0+7]));
        *(ulonglong2*)(Ms + (r0 + i) * 132 + c0)     = m01;
        *(ulonglong2*)(Ms + (r0 + i) * 132 + c0 + 4) = m23;
    }
    for (int idx = tid; idx < 128 * 32; idx += 256)
        ((float4*)Bs)[idx] = ((const float4*)W_fc)[idx];
    __syncthreads();

#pragma unroll
    for (int i = 0; i < 32; i++) acc[i] = 0ULL;
    {
        const float* Arow = Ms + r0 * 132;
        const float* Bc   = Bs + c0;
#pragma unroll 2
        for (int k = 0; k < 128; k++) gemm_step8<132>(Arow, Bc + k * 128, k, acc);
    }
#pragma unroll
    for (int i = 0; i < 8; i++) {
        if (base + r0 + i < N_ATOMS) {
            float* orow = out + (size_t)(base + r0 + i) * N_EMB + c0;
            const float* af = Af + (r0 + i) * 132 + c0;
#pragma unroll
            for (int q = 0; q < 4; q++) {
                float lo, hi; unpack2(acc[i * 4 + q], lo, hi);
                orow[2 * q]     = af[2 * q]     - fast_tanh(lo);
                orow[2 * q + 1] = af[2 * q + 1] - fast_tanh(hi);
            }
        }
    }
}

// =====================================================================
// Warp GEMM: D[256,128] over 16 warps (4 row-groups x 4 col-groups).
// Warp tile 64x32: 4 m16 tiles x 4 n8 tiles, 3-term bf16 split.
// =====================================================================
template<int KSTEPS>
static __device__ __forceinline__ void do_gemm(
    uint32_t aHi, uint32_t aLo, uint32_t bHi, uint32_t bLo,
    uint32_t aoff0, uint32_t boff0, float* d)
{
#pragma unroll 1
    for (int ks = 0; ks < KSTEPS; ks++) {
        uint32_t Ah[4][4], Al[4][4], Bh[4][2], Bl[4][2];
#pragma unroll
        for (int mt = 0; mt < 4; mt++) {
            uint32_t off = aoff0 + mt * (16 * BSTR * 2) + ks * 32;
            ldsm4(Ah[mt], aHi + off);
            ldsm4(Al[mt], aLo + off);
        }
#pragma unroll
        for (int np = 0; np < 2; np++) {
            uint32_t off = boff0 + np * (16 * BSTR * 2) + ks * 32;
            uint32_t th[4], tl[4];
            ldsm4(th, bHi + off);
            ldsm4(tl, bLo + off);
            Bh[2*np][0] = th[0]; Bh[2*np][1] = th[1];
            Bh[2*np+1][0] = th[2]; Bh[2*np+1][1] = th[3];
            Bl[2*np][0] = tl[0]; Bl[2*np][1] = tl[1];
            Bl[2*np+1][0] = tl[2]; Bl[2*np+1][1] = tl[3];
        }
#pragma unroll
        for (int mt = 0; mt < 4; mt++)
#pragma unroll
            for (int nt = 0; nt < 4; nt++) {
                float* dd = d + (mt * 4 + nt) * 4;
                mma16816(dd, Ah[mt], Bh[nt]);   // hi*hi
                mma16816(dd, Ah[mt], Bl[nt]);   // hi*lo
                mma16816(dd, Al[mt], Bh[nt]);   // lo*hi
            }
    }
}

// =====================================================================
// Pairs kernel: 512 thr = 16 warps, 256-pair tile, B swapped per GEMM.
// =====================================================================
__global__ void __launch_bounds__(512, 1) pairs_kernel(
    const float* __restrict__ distance,
    const int*   __restrict__ dmi,
    const int*   __restrict__ dmj,
    const float* __restrict__ b_df,
    float* __restrict__ out)
{
    extern __shared__ char smc[];
    int*   i_s   = (int*)(smc + SM_IS);
    int*   j_s   = (int*)(smc + SM_JS);
    float* bdf_s = (float*)(smc + SM_BDF);
    const uint32_t sb  = smem_u32(smc);
    const uint32_t aHi = sb + SM_AHI, aLo = sb + SM_ALO;
    const uint32_t bHi = sb + SM_BHI, bLo = sb + SM_BLO;

    const int tid = threadIdx.x;
    const int wid = tid >> 5, lane = tid & 31;
    const int rg = wid >> 2, cg = wid & 3;      // 4 x 4 warp grid
    const int pbase = blockIdx.x * TROWS;

    // ---- stage: distance splits (2 thr/row) + W_df images + indices ----
    {
        const int srow  = tid >> 1;             // 0..255
        const int shalf = tid & 1;
        if (!shalf) {
            i_s[srow]  = dmi[pbase + srow];
            j_s[srow]  = dmj[pbase + srow];
            if (srow < 128) bdf_s[srow] = b_df[srow];
        }
        const float4* dr =
            (const float4*)(distance + (size_t)(pbase + srow) * N_DIST);
        char* ah = smc + SM_AHI + srow * (BSTR * 2);
        char* al = smc + SM_ALO + srow * (BSTR * 2);
        const int q0 = shalf ? 13 : 0;
        const int q1 = shalf ? 25 : 13;
#pragma unroll
        for (int q = q0; q < q1; q++) {
            float4 v = dr[q];
            ushort_t h0,l0,h1,l1,h2,l2,h3,l3;
            split_bf(v.x, h0, l0); split_bf(v.y, h1, l1);
            split_bf(v.z, h2, l2); split_bf(v.w, h3, l3);
            *(unsigned*)(ah + 8 * q)     = (unsigned)h0 | ((unsigned)h1 << 16);
            *(unsigned*)(ah + 8 * q + 4) = (unsigned)h2 | ((unsigned)h3 << 16);
            *(unsigned*)(al + 8 * q)     = (unsigned)l0 | ((unsigned)l1 << 16);
            *(unsigned*)(al + 8 * q + 4) = (unsigned)l2 | ((unsigned)l3 << 16);
        }
        if (shalf) {
#pragma unroll
            for (int c = 100; c < 112; c += 2) {   // zero pad (kstep 6)
                *(unsigned*)(ah + c * 2) = 0u;
                *(unsigned*)(al + c * 2) = 0u;
            }
        }
        // W_df images (all 512 threads co-stage)
        for (int q = tid; q < 2176; q += 512) {
            ((uint4*)(smc + SM_BHI))[q] = ((const uint4*)g_Bdf_hi)[q];
            ((uint4*)(smc + SM_BLO))[q] = ((const uint4*)g_Bdf_lo)[q];
        }
    }
    __syncthreads();

    // lane-level ldmatrix address components
    const int arow  = (lane & 7) + 8 * ((lane >> 3) & 1);
    const int acolb = 16 * (lane >> 4);
    const int brow  = (lane & 7) + 8 * (lane >> 4);
    const int bcolb = 16 * ((lane >> 3) & 1);
    const uint32_t aoff0 = (uint32_t)((rg * 64 + arow) * (BSTR * 2) + acolb);
    const uint32_t boff0 = (uint32_t)((cg * 32 + brow) * (BSTR * 2) + bcolb);

    float d[64];
#pragma unroll
    for (int i = 0; i < 64; i++) d[i] = 0.0f;

    // ---- GEMM1: dh = dist @ W_df (K=112 incl. zero pad) ----
    do_gemm<7>(aHi, aLo, bHi, bLo, aoff0, boff0, d);
    __syncthreads();   // all ldsm reads done before A/B overwrite

    // ---- Epilogue 1: m = (dh + b_df) * afh[j]; resplit into A ----
    {
        const int g = lane >> 2, tg = lane & 3;
#pragma unroll
        for (int mt = 0; mt < 4; mt++)
#pragma unroll
            for (int f2 = 0; f2 < 2; f2++) {
                const int row = rg * 64 + mt * 16 + 8 * f2 + g;
                const int j = j_s[row];
                const float* ar = g_afh + (size_t)j * N_HID;
                char* ah = smc + SM_AHI + row * (BSTR * 2);
                char* al = smc + SM_ALO + row * (BSTR * 2);
#pragma unroll
                for (int nt = 0; nt < 4; nt++) {
                    const int c = cg * 32 + nt * 8 + 2 * tg;
                    float2 af = *(const float2*)(ar + c);
                    float v0 = (d[(mt*4+nt)*4 + 2*f2]     + bdf_s[c])     * af.x;
                    float v1 = (d[(mt*4+nt)*4 + 2*f2 + 1] + bdf_s[c + 1]) * af.y;
                    ushort_t h0, l0, h1, l1;
                    split_bf(v0, h0, l0); split_bf(v1, h1, l1);
                    *(unsigned*)(ah + c * 2) = (unsigned)h0 | ((unsigned)h1 << 16);
                    *(unsigned*)(al + c * 2) = (unsigned)l0 | ((unsigned)l1 << 16);
                }
            }
    }
    // swap in W_fc images
    for (int q = tid; q < 2176; q += 512) {
        ((uint4*)(smc + SM_BHI))[q] = ((const uint4*)g_Bfc_hi)[q];
        ((uint4*)(smc + SM_BLO))[q] = ((const uint4*)g_Bfc_lo)[q];
    }
    __syncthreads();

    // ---- GEMM2: pre = m @ W_fc (K=128) ----
#pragma unroll
    for (int i = 0; i < 64; i++) d[i] = 0.0f;
    do_gemm<8>(aHi, aLo, bHi, bLo, aoff0, boff0, d);
    __syncthreads();   // A-region ldsm done before msg overwrite

    // ---- Epilogue 2: msg = tanh(pre) -> A region ----
    {
        float* msg = (float*)(smc + SM_MSG);
        const int g = lane >> 2, tg = lane & 3;
#pragma unroll
        for (int mt = 0; mt < 4; mt++)
#pragma unroll
            for (int f2 = 0; f2 < 2; f2++) {
                const int row = rg * 64 + mt * 16 + 8 * f2 + g;
#pragma unroll
                for (int nt = 0; nt < 4; nt++) {
                    const int c = cg * 32 + nt * 8 + 2 * tg;
                    msg[row * 129 + c]     = fast_tanh(d[(mt*4+nt)*4 + 2*f2]);
                    msg[row * 129 + c + 1] = fast_tanh(d[(mt*4+nt)*4 + 2*f2 + 1]);
                }
            }
    }
    __syncthreads();

    // ---- Segment sum over sorted i: 512 thr = 128 cols x 4 quarters ----
    {
        const float* msg = (const float*)(smc + SM_MSG);
        const int c  = tid & 127;
        const int h0 = (tid >> 7) * 64;   // 0, 64, 128, 192
        int   cur = i_s[h0];
        float sum = 0.0f;
        for (int rr = h0; rr < h0 + 64; rr++) {
            int ii = i_s[rr];
            if (ii != cur) {
                atomicAdd(out + (size_t)cur * N_EMB + c, sum);
                cur = ii; sum = 0.0f;
            }
            sum += msg[rr * 129 + c];
        }
        atomicAdd(out + (size_t)cur * N_EMB + c, sum);
    }
}

// =====================================================================
extern "C" void kernel_launch(void* const* d_in, const int* in_sizes, int n_in,
                              void* d_out, int out_size)
{
    const float* atom_features = (const float*)d_in[0];
    const float* distance      = (const float*)d_in[1];
    const int*   dmi           = (const int*)d_in[3];
    const int*   dmj           = (const int*)d_in[4];
    const float* W_cf          = (const float*)d_in[5];
    const float* W_df          = (const float*)d_in[6];
    const float* W_fc          = (const float*)d_in[7];
    const float* b_cf          = (const float*)d_in[8];
    const float* b_df          = (const float*)d_in[9];
    float*       out           = (float*)d_out;

    const int smemA = (256 + 128*132 + 128*132 + 128*128) * 4;   // 201728 B

    cudaFuncSetAttribute(atoms_kernel, cudaFuncAttributeMaxDynamicSharedMemorySize, smemA);
    cudaFuncSetAttribute(pairs_kernel, cudaFuncAttributeMaxDynamicSharedMemorySize, SM_TOTAL);

    prep_kernel<<<64, 256>>>(W_df, W_fc);
    atoms_kernel<<<(N_ATOMS + 127) / 128, 256, smemA>>>(
        atom_features, W_cf, W_fc, b_cf, b_df, out);
    pairs_kernel<<<N_PAIRS / TROWS, 512, SM_TOTAL>>>(
        distance, dmi, dmj, b_df, out);
}

// round 9
// speedup vs baseline: 1.4054x; 1.0679x over previous
#include <cuda_runtime.h>
#include <cuda_bf16.h>
#include <cstdint>

#define N_ATOMS 50000
#define N_PAIRS 800000
#define N_EMB   128
#define N_DIST  100
#define N_HID   128
#define BSTR    136          // padded bf16 row stride (272 B)
#define TROWS   256          // rows per CTA tile (pairs & atoms)

typedef unsigned long long ull;
typedef unsigned short ushort_t;

// ---------------- device scratch ----------------
// afh packed as bf16 hi|lo<<16 per element (12.8 MB)
__device__ __align__(16) unsigned g_afh2[(size_t)N_ATOMS * N_HID];
__device__ __align__(16) __nv_bfloat16 g_Bdf_hi[128 * BSTR];
__device__ __align__(16) __nv_bfloat16 g_Bdf_lo[128 * BSTR];
__device__ __align__(16) __nv_bfloat16 g_Bfc_hi[128 * BSTR];
__device__ __align__(16) __nv_bfloat16 g_Bfc_lo[128 * BSTR];
__device__ __align__(16) __nv_bfloat16 g_Bcf_hi[128 * BSTR];
__device__ __align__(16) __nv_bfloat16 g_Bcf_lo[128 * BSTR];

// ---------------- helpers ----------------
static __device__ __forceinline__ float fast_tanh(float x) {
    float e = __expf(2.0f * x);
    return 1.0f - __fdividef(2.0f, e + 1.0f);
}
static __device__ __forceinline__ void split_bf(float x, ushort_t &h, ushort_t &l) {
    __nv_bfloat16 bh = __float2bfloat16(x);
    float r = x - __bfloat162float(bh);
    __nv_bfloat16 bl = __float2bfloat16(r);
    h = __bfloat16_as_ushort(bh);
    l = __bfloat16_as_ushort(bl);
}
static __device__ __forceinline__ float unsplit(unsigned p) {
    return __bfloat162float(__ushort_as_bfloat16((ushort_t)(p & 0xFFFF)))
         + __bfloat162float(__ushort_as_bfloat16((ushort_t)(p >> 16)));
}
static __device__ __forceinline__ uint32_t smem_u32(const void* p) {
    uint32_t a;
    asm("{ .reg .u64 t; cvta.to.shared.u64 t, %1; cvt.u32.u64 %0, t; }"
        : "=r"(a) : "l"(p));
    return a;
}
static __device__ __forceinline__ void ldsm4(uint32_t* r, uint32_t addr) {
    asm volatile("ldmatrix.sync.aligned.m8n8.x4.shared.b16 {%0,%1,%2,%3}, [%4];"
                 : "=r"(r[0]), "=r"(r[1]), "=r"(r[2]), "=r"(r[3]) : "r"(addr));
}
static __device__ __forceinline__ void mma16816(float* d, const uint32_t* a,
                                                const uint32_t* b) {
    asm volatile(
        "mma.sync.aligned.m16n8k16.row.col.f32.bf16.bf16.f32 "
        "{%0,%1,%2,%3}, {%4,%5,%6,%7}, {%8,%9}, {%0,%1,%2,%3};"
        : "+f"(d[0]), "+f"(d[1]), "+f"(d[2]), "+f"(d[3])
        : "r"(a[0]), "r"(a[1]), "r"(a[2]), "r"(a[3]), "r"(b[0]), "r"(b[1]));
}

// ---------------- SMEM layout (shared by both big kernels, bytes) --------
#define SM_IS    0                         // 256 int / b_cf area
#define SM_JS    1024                      // 256 int / b_df area
#define SM_BDF   2048                      // 128 float
#define SM_AHI   2560                      // 256 x 136 bf16 = 69632 B
#define SM_ALO   (SM_AHI + 69632)          // 72192
#define SM_BHI   (SM_ALO + 69632)          // 141824 (34816 B)
#define SM_BLO   (SM_BHI + 34816)          // 176640 (34816 B)
#define SM_TOTAL (SM_BLO + 34816)          // 211456 B
#define SM_MSG   SM_AHI                    // fp32 msg 256x129 reuses A

// =====================================================================
// Prep: n-major padded bf16 hi/lo images of W_df^T, W_fc^T, W_cf^T
// =====================================================================
__global__ void prep_kernel(const float* __restrict__ W_df,
                            const float* __restrict__ W_fc,
                            const float* __restrict__ W_cf)
{
    int idx = blockIdx.x * blockDim.x + threadIdx.x;   // 0..16383
    if (idx >= 16384) return;
    int n = idx >> 7;
    int k = idx & 127;
    int o = n * BSTR + k;
    ushort_t h, l;
    float vdf = (k < N_DIST) ? W_df[k * 128 + n] : 0.0f;
    split_bf(vdf, h, l);
    g_Bdf_hi[o] = __ushort_as_bfloat16(h);
    g_Bdf_lo[o] = __ushort_as_bfloat16(l);
    split_bf(W_fc[k * 128 + n], h, l);
    g_Bfc_hi[o] = __ushort_as_bfloat16(h);
    g_Bfc_lo[o] = __ushort_as_bfloat16(l);
    split_bf(W_cf[k * 128 + n], h, l);
    g_Bcf_hi[o] = __ushort_as_bfloat16(h);
    g_Bcf_lo[o] = __ushort_as_bfloat16(l);
}

// =====================================================================
// Warp GEMM: D[256,128] over 16 warps (4 rg x 4 cg), warp tile 64x32.
// 3-term bf16 split: hi*hi + hi*lo + lo*hi.
// =====================================================================
template<int KSTEPS>
static __device__ __forceinline__ void do_gemm(
    uint32_t aHi, uint32_t aLo, uint32_t bHi, uint32_t bLo,
    uint32_t aoff0, uint32_t boff0, float* d)
{
#pragma unroll 1
    for (int ks = 0; ks < KSTEPS; ks++) {
        uint32_t Ah[4][4], Al[4][4], Bh[4][2], Bl[4][2];
#pragma unroll
        for (int mt = 0; mt < 4; mt++) {
            uint32_t off = aoff0 + mt * (16 * BSTR * 2) + ks * 32;
            ldsm4(Ah[mt], aHi + off);
            ldsm4(Al[mt], aLo + off);
        }
#pragma unroll
        for (int np = 0; np < 2; np++) {
            uint32_t off = boff0 + np * (16 * BSTR * 2) + ks * 32;
            uint32_t th[4], tl[4];
            ldsm4(th, bHi + off);
            ldsm4(tl, bLo + off);
            Bh[2*np][0] = th[0]; Bh[2*np][1] = th[1];
            Bh[2*np+1][0] = th[2]; Bh[2*np+1][1] = th[3];
            Bl[2*np][0] = tl[0]; Bl[2*np][1] = tl[1];
            Bl[2*np+1][0] = tl[2]; Bl[2*np+1][1] = tl[3];
        }
#pragma unroll
        for (int mt = 0; mt < 4; mt++)
#pragma unroll
            for (int nt = 0; nt < 4; nt++) {
                float* dd = d + (mt * 4 + nt) * 4;
                mma16816(dd, Ah[mt], Bh[nt]);
                mma16816(dd, Ah[mt], Bl[nt]);
                mma16816(dd, Al[mt], Bh[nt]);
            }
    }
}

// Stage a 256-row fp32 matrix (row length 128, zero-fill beyond nrows)
// as bf16 hi/lo splits. 2 threads per row.
static __device__ __forceinline__ void stage_splits(
    char* smc, const float* __restrict__ src, int base, int nrows,
    int tid, int ncols /* 100 or 128 */)
{
    const int srow  = tid >> 1;
    const int shalf = tid & 1;
    const int nq = ncols / 4;                 // 25 or 32
    const int q0 = shalf ? (nq + 1) / 2 : 0;  // 13/16
    const int q1 = shalf ? nq : (nq + 1) / 2;
    char* ah = smc + SM_AHI + srow * (BSTR * 2);
    char* al = smc + SM_ALO + srow * (BSTR * 2);
    if (srow < nrows) {
        const float4* dr = (const float4*)(src + (size_t)(base + srow) * ncols);
#pragma unroll
        for (int q = q0; q < q1; q++) {
            float4 v = dr[q];
            ushort_t h0,l0,h1,l1,h2,l2,h3,l3;
            split_bf(v.x, h0, l0); split_bf(v.y, h1, l1);
            split_bf(v.z, h2, l2); split_bf(v.w, h3, l3);
            *(unsigned*)(ah + 8 * q)     = (unsigned)h0 | ((unsigned)h1 << 16);
            *(unsigned*)(ah + 8 * q + 4) = (unsigned)h2 | ((unsigned)h3 << 16);
            *(unsigned*)(al + 8 * q)     = (unsigned)l0 | ((unsigned)l1 << 16);
            *(unsigned*)(al + 8 * q + 4) = (unsigned)l2 | ((unsigned)l3 << 16);
        }
    } else {
        for (int q = q0; q < q1; q++) {
            *(ull*)(ah + 8 * q) = 0ULL;
            *(ull*)(al + 8 * q) = 0ULL;
        }
    }
    if (ncols < 128 && shalf) {
#pragma unroll
        for (int c = 100; c < 112; c += 2) {   // zero pad (kstep 6)
            *(unsigned*)(ah + c * 2) = 0u;
            *(unsigned*)(al + c * 2) = 0u;
        }
    }
}

// =====================================================================
// Atoms kernel (HMMA): per 256-atom tile
//   afh = A @ W_cf + b_cf   -> g_afh2 (packed bf16 hi/lo)
//   out = A - tanh((b_df * afh) @ W_fc)
// =====================================================================
__global__ void __launch_bounds__(512, 1) atoms_kernel(
    const float* __restrict__ atom_features,
    const float* __restrict__ b_cf,
    const float* __restrict__ b_df,
    float* __restrict__ out)
{
    extern __shared__ char smc[];
    float* bcf_s = (float*)(smc + SM_IS);
    float* bdf_s = (float*)(smc + SM_JS);
    const uint32_t sb  = smem_u32(smc);
    const uint32_t aHi = sb + SM_AHI, aLo = sb + SM_ALO;
    const uint32_t bHi = sb + SM_BHI, bLo = sb + SM_BLO;

    const int tid = threadIdx.x;
    const int wid = tid >> 5, lane = tid & 31;
    const int rg = wid >> 2, cg = wid & 3;
    const int base  = blockIdx.x * TROWS;
    const int nrows = min(TROWS, N_ATOMS - base);

    if (tid < 128) { bcf_s[tid] = b_cf[tid]; bdf_s[tid] = b_df[tid]; }
    stage_splits(smc, atom_features, base, nrows, tid, 128);
    for (int q = tid; q < 2176; q += 512) {
        ((uint4*)(smc + SM_BHI))[q] = ((const uint4*)g_Bcf_hi)[q];
        ((uint4*)(smc + SM_BLO))[q] = ((const uint4*)g_Bcf_lo)[q];
    }
    __syncthreads();

    const int arow  = (lane & 7) + 8 * ((lane >> 3) & 1);
    const int acolb = 16 * (lane >> 4);
    const int brow  = (lane & 7) + 8 * (lane >> 4);
    const int bcolb = 16 * ((lane >> 3) & 1);
    const uint32_t aoff0 = (uint32_t)((rg * 64 + arow) * (BSTR * 2) + acolb);
    const uint32_t boff0 = (uint32_t)((cg * 32 + brow) * (BSTR * 2) + bcolb);

    float d[64];
#pragma unroll
    for (int i = 0; i < 64; i++) d[i] = 0.0f;
    do_gemm<8>(aHi, aLo, bHi, bLo, aoff0, boff0, d);
    __syncthreads();

    // Epilogue 1: afh = d + b_cf -> g_afh2 (packed); m = b_df*afh -> A splits
    {
        const int g = lane >> 2, tg = lane & 3;
#pragma unroll
        for (int mt = 0; mt < 4; mt++)
#pragma unroll
            for (int f2 = 0; f2 < 2; f2++) {
                const int row = rg * 64 + mt * 16 + 8 * f2 + g;
                const bool ok = row < nrows;
                char* ah = smc + SM_AHI + row * (BSTR * 2);
                char* al = smc + SM_ALO + row * (BSTR * 2);
                unsigned* g2 = g_afh2 + (size_t)(base + row) * N_HID;
#pragma unroll
                for (int nt = 0; nt < 4; nt++) {
                    const int c = cg * 32 + nt * 8 + 2 * tg;
                    float a0 = d[(mt*4+nt)*4 + 2*f2]     + bcf_s[c];
                    float a1 = d[(mt*4+nt)*4 + 2*f2 + 1] + bcf_s[c + 1];
                    ushort_t h0, l0, h1, l1;
                    split_bf(a0, h0, l0); split_bf(a1, h1, l1);
                    if (ok) {
                        uint2 pk;
                        pk.x = (unsigned)h0 | ((unsigned)l0 << 16);
                        pk.y = (unsigned)h1 | ((unsigned)l1 << 16);
                        *(uint2*)(g2 + c) = pk;
                    }
                    float m0 = bdf_s[c] * a0, m1 = bdf_s[c + 1] * a1;
                    split_bf(m0, h0, l0); split_bf(m1, h1, l1);
                    *(unsigned*)(ah + c * 2) = (unsigned)h0 | ((unsigned)h1 << 16);
                    *(unsigned*)(al + c * 2) = (unsigned)l0 | ((unsigned)l1 << 16);
                }
            }
    }
    for (int q = tid; q < 2176; q += 512) {
        ((uint4*)(smc + SM_BHI))[q] = ((const uint4*)g_Bfc_hi)[q];
        ((uint4*)(smc + SM_BLO))[q] = ((const uint4*)g_Bfc_lo)[q];
    }
    __syncthreads();

#pragma unroll
    for (int i = 0; i < 64; i++) d[i] = 0.0f;
    do_gemm<8>(aHi, aLo, bHi, bLo, aoff0, boff0, d);

    // Epilogue 2: out = atom_features - tanh(pre)   (af reloaded from gmem)
    {
        const int g = lane >> 2, tg = lane & 3;
#pragma unroll
        for (int mt = 0; mt < 4; mt++)
#pragma unroll
            for (int f2 = 0; f2 < 2; f2++) {
                const int row = rg * 64 + mt * 16 + 8 * f2 + g;
                if (row < nrows) {
                    const float* afr = atom_features + (size_t)(base + row) * N_EMB;
                    float* orow = out + (size_t)(base + row) * N_EMB;
#pragma unroll
                    for (int nt = 0; nt < 4; nt++) {
                        const int c = cg * 32 + nt * 8 + 2 * tg;
                        float2 af = *(const float2*)(afr + c);
                        float2 ov;
                        ov.x = af.x - fast_tanh(d[(mt*4+nt)*4 + 2*f2]);
                        ov.y = af.y - fast_tanh(d[(mt*4+nt)*4 + 2*f2 + 1]);
                        *(float2*)(orow + c) = ov;
                    }
                }
            }
    }
}

// =====================================================================
// Pairs kernel: 512 thr = 16 warps, 256-pair tile (R8 skeleton).
// =====================================================================
__global__ void __launch_bounds__(512, 1) pairs_kernel(
    const float* __restrict__ distance,
    const int*   __restrict__ dmi,
    const int*   __restrict__ dmj,
    const float* __restrict__ b_df,
    float* __restrict__ out)
{
    extern __shared__ char smc[];
    int*   i_s   = (int*)(smc + SM_IS);
    int*   j_s   = (int*)(smc + SM_JS);
    float* bdf_s = (float*)(smc + SM_BDF);
    const uint32_t sb  = smem_u32(smc);
    const uint32_t aHi = sb + SM_AHI, aLo = sb + SM_ALO;
    const uint32_t bHi = sb + SM_BHI, bLo = sb + SM_BLO;

    const int tid = threadIdx.x;
    const int wid = tid >> 5, lane = tid & 31;
    const int rg = wid >> 2, cg = wid & 3;
    const int pbase = blockIdx.x * TROWS;

    {
        const int srow  = tid >> 1;
        const int shalf = tid & 1;
        if (!shalf) {
            i_s[srow]  = dmi[pbase + srow];
            j_s[srow]  = dmj[pbase + srow];
            if (srow < 128) bdf_s[srow] = b_df[srow];
        }
    }
    stage_splits(smc, distance, pbase, TROWS, tid, N_DIST);
    for (int q = tid; q < 2176; q += 512) {
        ((uint4*)(smc + SM_BHI))[q] = ((const uint4*)g_Bdf_hi)[q];
        ((uint4*)(smc + SM_BLO))[q] = ((const uint4*)g_Bdf_lo)[q];
    }
    __syncthreads();

    const int arow  = (lane & 7) + 8 * ((lane >> 3) & 1);
    const int acolb = 16 * (lane >> 4);
    const int brow  = (lane & 7) + 8 * (lane >> 4);
    const int bcolb = 16 * ((lane >> 3) & 1);
    const uint32_t aoff0 = (uint32_t)((rg * 64 + arow) * (BSTR * 2) + acolb);
    const uint32_t boff0 = (uint32_t)((cg * 32 + brow) * (BSTR * 2) + bcolb);

    float d[64];
#pragma unroll
    for (int i = 0; i < 64; i++) d[i] = 0.0f;

    // GEMM1: dh = dist @ W_df (K=112 incl. zero pad)
    do_gemm<7>(aHi, aLo, bHi, bLo, aoff0, boff0, d);
    __syncthreads();

    // Epilogue 1: m = (dh + b_df) * afh[j] (packed gather); resplit into A
    {
        const int g = lane >> 2, tg = lane & 3;
#pragma unroll
        for (int mt = 0; mt < 4; mt++)
#pragma unroll
            for (int f2 = 0; f2 < 2; f2++) {
                const int row = rg * 64 + mt * 16 + 8 * f2 + g;
                const int j = j_s[row];
                const unsigned* ar = g_afh2 + (size_t)j * N_HID;
                char* ah = smc + SM_AHI + row * (BSTR * 2);
                char* al = smc + SM_ALO + row * (BSTR * 2);
#pragma unroll
                for (int nt = 0; nt < 4; nt++) {
                    const int c = cg * 32 + nt * 8 + 2 * tg;
                    uint2 pk = *(const uint2*)(ar + c);
                    float v0 = (d[(mt*4+nt)*4 + 2*f2]     + bdf_s[c])     * unsplit(pk.x);
                    float v1 = (d[(mt*4+nt)*4 + 2*f2 + 1] + bdf_s[c + 1]) * unsplit(pk.y);
                    ushort_t h0, l0, h1, l1;
                    split_bf(v0, h0, l0); split_bf(v1, h1, l1);
                    *(unsigned*)(ah + c * 2) = (unsigned)h0 | ((unsigned)h1 << 16);
                    *(unsigned*)(al + c * 2) = (unsigned)l0 | ((unsigned)l1 << 16);
                }
            }
    }
    for (int q = tid; q < 2176; q += 512) {
        ((uint4*)(smc + SM_BHI))[q] = ((const uint4*)g_Bfc_hi)[q];
        ((uint4*)(smc + SM_BLO))[q] = ((const uint4*)g_Bfc_lo)[q];
    }
    __syncthreads();

    // GEMM2: pre = m @ W_fc (K=128)
#pragma unroll
    for (int i = 0; i < 64; i++) d[i] = 0.0f;
    do_gemm<8>(aHi, aLo, bHi, bLo, aoff0, boff0, d);
    __syncthreads();

    // Epilogue 2: msg = tanh(pre) -> A region
    {
        float* msg = (float*)(smc + SM_MSG);
        const int g = lane >> 2, tg = lane & 3;
#pragma unroll
        for (int mt = 0; mt < 4; mt++)
#pragma unroll
            for (int f2 = 0; f2 < 2; f2++) {
                const int row = rg * 64 + mt * 16 + 8 * f2 + g;
#pragma unroll
                for (int nt = 0; nt < 4; nt++) {
                    const int c = cg * 32 + nt * 8 + 2 * tg;
                    msg[row * 129 + c]     = fast_tanh(d[(mt*4+nt)*4 + 2*f2]);
                    msg[row * 129 + c + 1] = fast_tanh(d[(mt*4+nt)*4 + 2*f2 + 1]);
                }
            }
    }
    __syncthreads();

    // Segment sum over sorted i: 512 thr = 128 cols x 4 quarters
    {
        const float* msg = (const float*)(smc + SM_MSG);
        const int c  = tid & 127;
        const int h0 = (tid >> 7) * 64;
        int   cur = i_s[h0];
        float sum = 0.0f;
        for (int rr = h0; rr < h0 + 64; rr++) {
            int ii = i_s[rr];
            if (ii != cur) {
                atomicAdd(out + (size_t)cur * N_EMB + c, sum);
                cur = ii; sum = 0.0f;
            }
            sum += msg[rr * 129 + c];
        }
        atomicAdd(out + (size_t)cur * N_EMB + c, sum);
    }
}

// =====================================================================
extern "C" void kernel_launch(void* const* d_in, const int* in_sizes, int n_in,
                              void* d_out, int out_size)
{
    const float* atom_features = (const float*)d_in[0];
    const float* distance      = (const float*)d_in[1];
    const int*   dmi           = (const int*)d_in[3];
    const int*   dmj           = (const int*)d_in[4];
    const float* W_cf          = (const float*)d_in[5];
    const float* W_df          = (const float*)d_in[6];
    const float* W_fc          = (const float*)d_in[7];
    const float* b_cf          = (const float*)d_in[8];
    const float* b_df          = (const float*)d_in[9];
    float*       out           = (float*)d_out;

    cudaFuncSetAttribute(atoms_kernel, cudaFuncAttributeMaxDynamicSharedMemorySize, SM_TOTAL);
    cudaFuncSetAttribute(pairs_kernel, cudaFuncAttributeMaxDynamicSharedMemorySize, SM_TOTAL);

    prep_kernel<<<64, 256>>>(W_df, W_fc, W_cf);
    atoms_kernel<<<(N_ATOMS + TROWS - 1) / TROWS, 512, SM_TOTAL>>>(
        atom_features, b_cf, b_df, out);
    pairs_kernel<<<N_PAIRS / TROWS, 512, SM_TOTAL>>>(
        distance, dmi, dmj, b_df, out);
}